// round 3
// baseline (speedup 1.0000x reference)
#include <cuda_runtime.h>
#include <cuda_bf16.h>
#include <cstdint>

// Problem constants
#define BB 2
#define HH 192
#define WW 192
#define CC 192
#define WS 16
#define SHIFT 8
#define NH 6
#define HD 32
#define NTOK 256          // tokens per window
#define NWSIDE 12         // windows per side
#define NWB 144           // windows per batch
#define NWIN 288          // total windows
#define QK_SCALE 0.17677669529663687f  // 32^-0.5

// Scratch (static __device__ globals: allowed, allocated at module load)
__device__ float g_cth[NWIN * NTOK];
__device__ float g_ctv[NWIN * NTOK];
__device__ float g_ow[(size_t)NWIN * NTOK * CC];   // attention output before projection (56.6 MB)

__device__ __forceinline__ int wrapH(int hs) { int h = hs + SHIFT; return (h >= HH) ? h - HH : h; }

// ---------------------------------------------------------------------------
// Kernel 1: per-window geo cumulative tables cth/ctv
// ---------------------------------------------------------------------------
__global__ void __launch_bounds__(256) geo_kernel(const float* __restrict__ x,
                                                  const float* __restrict__ geo_sigma) {
    int win = blockIdx.x;
    int b = win / NWB, wr = (win % NWB) / NWSIDE, wc = win % NWSIDE;
    int tid = threadIdx.x;

    __shared__ float dh[16][16];   // dh[r][j], j<15
    __shared__ float dv[16][16];   // dv[i][c], i<15

    float sigma = fabsf(geo_sigma[0]);

    for (int p = tid; p < 480; p += 256) {
        int r0, c0, r1, c1; bool isH = (p < 240);
        if (isH) { int r = p / 15, j = p % 15; r0 = r; c0 = j; r1 = r; c1 = j + 1; }
        else     { int pp = p - 240; int i = pp / 16, c = pp % 16; r0 = i; c0 = c; r1 = i + 1; c1 = c; }
        int h0 = wrapH(wr * WS + r0), w0 = wrapH(wc * WS + c0);
        int h1 = wrapH(wr * WS + r1), w1 = wrapH(wc * WS + c1);
        const float* a  = x + ((size_t)((b * HH + h0) * WW + w0)) * CC;
        const float* bb = x + ((size_t)((b * HH + h1) * WW + w1)) * CC;
        float s = 0.f;
        #pragma unroll 4
        for (int ch = 0; ch < CC; ch += 4) {
            float4 av = *(const float4*)(a + ch);
            float4 bv = *(const float4*)(bb + ch);
            s += fabsf(bv.x - av.x) + fabsf(bv.y - av.y) + fabsf(bv.z - av.z) + fabsf(bv.w - av.w);
        }
        if (isH) dh[r0][c0] = s; else dv[r0][c0] = s;
    }
    __syncthreads();

    if (tid < 16) {                     // horizontal cumsum: cth[r][c]
        int r = tid; float acc = 0.f;
        g_cth[win * NTOK + r * 16 + 0] = 0.f;
        for (int c = 1; c < 16; c++) {
            acc += 1.f + sigma * dh[r][c - 1];
            g_cth[win * NTOK + r * 16 + c] = acc;
        }
    } else if (tid < 32) {              // vertical cumsum: ctv[r][c]
        int c = tid - 16; float acc = 0.f;
        g_ctv[win * NTOK + 0 * 16 + c] = 0.f;
        for (int r = 1; r < 16; r++) {
            acc += 1.f + sigma * dv[r - 1][c];
            g_ctv[win * NTOK + r * 16 + c] = acc;
        }
    }
}

// ---------------------------------------------------------------------------
// Kernel 2: attention per (window, head); one thread = one query row.
// No-max softmax (scores ~N(0,1) minus non-negative geo/mask bias: safe in fp32).
// rpi, attn_mask computed inline (no global reads in inner loop except none).
// ---------------------------------------------------------------------------
#define SMEM2_FLOATS (8192 + 8192 + 964 + 256 + 256 + 256)
#define SMEM2_BYTES  (SMEM2_FLOATS * 4)

__global__ void __launch_bounds__(256) attn_kernel(const float* __restrict__ qkv,
                                                   const float* __restrict__ rpb_table,
                                                   const float* __restrict__ geo_scale) {
    extern __shared__ float smem[];
    float* K_sh   = smem;                 // [256][32]
    float* V_sh   = K_sh + 8192;          // [256][32]
    float* rpb_sh = V_sh + 8192;          // [961] (pad 964)
    float* cth_sh = rpb_sh + 964;         // [256]
    float* ctv_sh = cth_sh + 256;         // [256]
    int*   reg_sh = (int*)(ctv_sh + 256); // [256]

    int win = blockIdx.x, head = blockIdx.y;
    int b = win / NWB, wr = (win % NWB) / NWSIDE, wc = win % NWSIDE;
    int q = threadIdx.x;
    int i = q >> 4, j = q & 15;
    int hs = wr * WS + i, ws = wc * WS + j;      // shifted-image coords
    int h = wrapH(hs), w = wrapH(ws);            // original coords

    const float* base = qkv + ((size_t)((b * HH + h) * WW + w)) * (3 * CC) + head * HD;

    float qreg[HD];
    #pragma unroll
    for (int d = 0; d < HD; d += 4) {
        float4 qv = *(const float4*)(base + d);
        qreg[d + 0] = qv.x * QK_SCALE; qreg[d + 1] = qv.y * QK_SCALE;
        qreg[d + 2] = qv.z * QK_SCALE; qreg[d + 3] = qv.w * QK_SCALE;
        *(float4*)(K_sh + q * HD + d) = *(const float4*)(base + CC + d);
        *(float4*)(V_sh + q * HD + d) = *(const float4*)(base + 2 * CC + d);
    }
    for (int t = q; t < 961; t += 256) rpb_sh[t] = rpb_table[t * NH + head];
    cth_sh[q] = g_cth[win * NTOK + q];
    ctv_sh[q] = g_ctv[win * NTOK + q];
    {   // shift-mask region id (on shifted coords)
        int rh = (hs < HH - WS) ? 0 : ((hs < HH - SHIFT) ? 1 : 2);
        int rw = (ws < WW - WS) ? 0 : ((ws < WW - SHIFT) ? 1 : 2);
        reg_sh[q] = rh * 3 + rw;
    }
    __syncthreads();

    float gsc  = geo_scale[head];
    float cthq = cth_sh[q];
    int myreg  = reg_sh[q];
    int qhi = q & 0xF0;
    int rq = q >> 4, cq = q & 15;

    float acc[HD];
    #pragma unroll
    for (int d = 0; d < HD; d++) acc[d] = 0.f;
    float l = 0.f;

    #pragma unroll 2
    for (int k = 0; k < NTOK; k++) {
        const float4* kr = (const float4*)(K_sh + (k << 5));
        float s0 = 0.f, s1 = 0.f, s2 = 0.f, s3 = 0.f;
        #pragma unroll
        for (int d = 0; d < 8; d++) {
            float4 kv = kr[d];
            s0 = fmaf(qreg[d * 4 + 0], kv.x, s0);
            s1 = fmaf(qreg[d * 4 + 1], kv.y, s1);
            s2 = fmaf(qreg[d * 4 + 2], kv.z, s2);
            s3 = fmaf(qreg[d * 4 + 3], kv.w, s3);
        }
        float dot = (s0 + s1) + (s2 + s3);

        int ck = k & 15, rk = k >> 4;
        int gi = qhi | ck;
        float geo = fabsf(cth_sh[gi] - cthq) + fabsf(ctv_sh[k] - ctv_sh[gi]);
        int ridx = (rq - rk + 15) * 31 + (cq - ck + 15);
        float s = dot + rpb_sh[ridx] - gsc * geo + ((myreg == reg_sh[k]) ? 0.f : -100.f);
        float p = __expf(s);
        l += p;

        const float4* vr = (const float4*)(V_sh + (k << 5));
        #pragma unroll
        for (int d = 0; d < 8; d++) {
            float4 vv = vr[d];
            acc[d * 4 + 0] = fmaf(p, vv.x, acc[d * 4 + 0]);
            acc[d * 4 + 1] = fmaf(p, vv.y, acc[d * 4 + 1]);
            acc[d * 4 + 2] = fmaf(p, vv.z, acc[d * 4 + 2]);
            acc[d * 4 + 3] = fmaf(p, vv.w, acc[d * 4 + 3]);
        }
    }

    float inv = 1.f / l;
    float* op = g_ow + (size_t)win * (NTOK * CC) + q * CC + head * HD;
    #pragma unroll
    for (int d = 0; d < HD; d += 4) {
        float4 r;
        r.x = acc[d + 0] * inv; r.y = acc[d + 1] * inv;
        r.z = acc[d + 2] * inv; r.w = acc[d + 3] * inv;
        *(float4*)(op + d) = r;
    }
}

// ---------------------------------------------------------------------------
// Kernel 3: projection (out_win @ proj_w.T + b) + window reverse + roll-back
// Block = 64 tokens; thread = 4 tokens x 12 output channels.
// ---------------------------------------------------------------------------
__global__ void __launch_bounds__(256) proj_kernel(const float* __restrict__ proj_w,
                                                   const float* __restrict__ proj_b,
                                                   float* __restrict__ out) {
    __shared__ float w_sh[32 * 196];   // [kk][cout], pad 196
    __shared__ float a_sh[64 * 33];    // [tok][kk], pad 33

    int blk = blockIdx.x, t = threadIdx.x;
    int tok0 = blk * 64;
    int tokl = (t & 15) * 4;
    int cob  = (t >> 4) * 12;

    float acc[48];
    #pragma unroll
    for (int e = 0; e < 48; e++) acc[e] = 0.f;

    for (int k0 = 0; k0 < CC; k0 += 32) {
        for (int e = t; e < 2048; e += 256) {
            int tk = e >> 5, kk = e & 31;
            a_sh[tk * 33 + kk] = g_ow[(size_t)(tok0 + tk) * CC + k0 + kk];
        }
        {
            int kk = t & 31;
            for (int co = t >> 5; co < CC; co += 8)
                w_sh[kk * 196 + co] = proj_w[co * CC + k0 + kk];
        }
        __syncthreads();

        #pragma unroll 4
        for (int kk = 0; kk < 32; kk++) {
            float a0 = a_sh[(tokl + 0) * 33 + kk];
            float a1 = a_sh[(tokl + 1) * 33 + kk];
            float a2 = a_sh[(tokl + 2) * 33 + kk];
            float a3 = a_sh[(tokl + 3) * 33 + kk];
            #pragma unroll
            for (int o = 0; o < 12; o += 4) {
                float4 wv = *(const float4*)(w_sh + kk * 196 + cob + o);
                acc[0 * 12 + o + 0] = fmaf(a0, wv.x, acc[0 * 12 + o + 0]);
                acc[0 * 12 + o + 1] = fmaf(a0, wv.y, acc[0 * 12 + o + 1]);
                acc[0 * 12 + o + 2] = fmaf(a0, wv.z, acc[0 * 12 + o + 2]);
                acc[0 * 12 + o + 3] = fmaf(a0, wv.w, acc[0 * 12 + o + 3]);
                acc[1 * 12 + o + 0] = fmaf(a1, wv.x, acc[1 * 12 + o + 0]);
                acc[1 * 12 + o + 1] = fmaf(a1, wv.y, acc[1 * 12 + o + 1]);
                acc[1 * 12 + o + 2] = fmaf(a1, wv.z, acc[1 * 12 + o + 2]);
                acc[1 * 12 + o + 3] = fmaf(a1, wv.w, acc[1 * 12 + o + 3]);
                acc[2 * 12 + o + 0] = fmaf(a2, wv.x, acc[2 * 12 + o + 0]);
                acc[2 * 12 + o + 1] = fmaf(a2, wv.y, acc[2 * 12 + o + 1]);
                acc[2 * 12 + o + 2] = fmaf(a2, wv.z, acc[2 * 12 + o + 2]);
                acc[2 * 12 + o + 3] = fmaf(a2, wv.w, acc[2 * 12 + o + 3]);
                acc[3 * 12 + o + 0] = fmaf(a3, wv.x, acc[3 * 12 + o + 0]);
                acc[3 * 12 + o + 1] = fmaf(a3, wv.y, acc[3 * 12 + o + 1]);
                acc[3 * 12 + o + 2] = fmaf(a3, wv.z, acc[3 * 12 + o + 2]);
                acc[3 * 12 + o + 3] = fmaf(a3, wv.w, acc[3 * 12 + o + 3]);
            }
        }
        __syncthreads();
    }

    #pragma unroll
    for (int ii = 0; ii < 4; ii++) {
        int g = tok0 + tokl + ii;
        int win = g >> 8, tt = g & 255;
        int b = win / NWB, wr = (win % NWB) / NWSIDE, wc = win % NWSIDE;
        int i = tt >> 4, jj = tt & 15;
        int h = wrapH(wr * WS + i), w = wrapH(wc * WS + jj);
        float* op = out + ((size_t)b * (HH * WW) + h * WW + w) * CC + cob;
        #pragma unroll
        for (int o = 0; o < 12; o += 4) {
            float4 r;
            r.x = acc[ii * 12 + o + 0] + proj_b[cob + o + 0];
            r.y = acc[ii * 12 + o + 1] + proj_b[cob + o + 1];
            r.z = acc[ii * 12 + o + 2] + proj_b[cob + o + 2];
            r.w = acc[ii * 12 + o + 3] + proj_b[cob + o + 3];
            *(float4*)(op + o) = r;
        }
    }
}

// ---------------------------------------------------------------------------
// Launch. Input order per metadata: x, qkv, rpb_table, geo_scale, geo_sigma,
// proj_w, proj_b, rpi (unused), attn_mask (unused), window_size, shift_size,
// num_heads (unused).
// ---------------------------------------------------------------------------
extern "C" void kernel_launch(void* const* d_in, const int* in_sizes, int n_in,
                              void* d_out, int out_size) {
    const float* x        = (const float*)d_in[0];
    const float* qkv      = (const float*)d_in[1];
    const float* rpb      = (const float*)d_in[2];
    const float* gscale   = (const float*)d_in[3];
    const float* gsigma   = (const float*)d_in[4];
    const float* proj_w   = (const float*)d_in[5];
    const float* proj_b   = (const float*)d_in[6];
    float* out            = (float*)d_out;

    cudaFuncSetAttribute(attn_kernel, cudaFuncAttributeMaxDynamicSharedMemorySize, SMEM2_BYTES);

    geo_kernel<<<NWIN, 256>>>(x, gsigma);
    attn_kernel<<<dim3(NWIN, NH), 256, SMEM2_BYTES>>>(qkv, rpb, gscale);
    proj_kernel<<<(NWIN * NTOK) / 64, 256>>>(proj_w, proj_b, out);
}

// round 6
// speedup vs baseline: 1.0689x; 1.0689x over previous
#include <cuda_runtime.h>
#include <cuda_bf16.h>
#include <cstdint>

// Problem constants
#define BB 2
#define HH 192
#define WW 192
#define CC 192
#define WS 16
#define SHIFT 8
#define NH 6
#define HD 32
#define NTOK 256          // tokens per window
#define NWSIDE 12         // windows per side
#define NWB 144           // windows per batch
#define NWIN 288          // total windows
#define QK_SCALE 0.17677669529663687f  // 32^-0.5

typedef unsigned long long u64;

// ---- packed fp32x2 helpers (sm_103a FFMA2 path; ptxas never emits these from C++) ----
__device__ __forceinline__ u64 ffma2(u64 a, u64 b, u64 c) {
    u64 d; asm("fma.rn.f32x2 %0, %1, %2, %3;" : "=l"(d) : "l"(a), "l"(b), "l"(c)); return d;
}
__device__ __forceinline__ u64 fmul2(u64 a, u64 b) {
    u64 d; asm("mul.rn.f32x2 %0, %1, %2;" : "=l"(d) : "l"(a), "l"(b)); return d;
}
__device__ __forceinline__ u64 fadd2(u64 a, u64 b) {
    u64 d; asm("add.rn.f32x2 %0, %1, %2;" : "=l"(d) : "l"(a), "l"(b)); return d;
}
__device__ __forceinline__ u64 pack2(float lo, float hi) {
    u64 r; asm("mov.b64 %0, {%1, %2};" : "=l"(r) : "f"(lo), "f"(hi)); return r;
}
__device__ __forceinline__ float2 unpack2(u64 v) {
    float2 f; asm("mov.b64 {%0, %1}, %2;" : "=f"(f.x), "=f"(f.y) : "l"(v)); return f;
}

// Scratch (static __device__ globals: allowed, allocated at module load)
__device__ float g_cth[NWIN * NTOK];
__device__ float g_ctv[NWIN * NTOK];
__device__ float g_ow[(size_t)NWIN * NTOK * CC];   // attention output before projection (56.6 MB)

__device__ __forceinline__ int wrapH(int hs) { int h = hs + SHIFT; return (h >= HH) ? h - HH : h; }

// ---------------------------------------------------------------------------
// Kernel 1: per-window geo cumulative tables cth/ctv (unchanged; 51us, not hot)
// ---------------------------------------------------------------------------
__global__ void __launch_bounds__(256) geo_kernel(const float* __restrict__ x,
                                                  const float* __restrict__ geo_sigma) {
    int win = blockIdx.x;
    int b = win / NWB, wr = (win % NWB) / NWSIDE, wc = win % NWSIDE;
    int tid = threadIdx.x;

    __shared__ float dh[16][16];   // dh[r][j], j<15
    __shared__ float dv[16][16];   // dv[i][c], i<15

    float sigma = fabsf(geo_sigma[0]);

    for (int p = tid; p < 480; p += 256) {
        int r0, c0, r1, c1; bool isH = (p < 240);
        if (isH) { int r = p / 15, j = p % 15; r0 = r; c0 = j; r1 = r; c1 = j + 1; }
        else     { int pp = p - 240; int i = pp / 16, c = pp % 16; r0 = i; c0 = c; r1 = i + 1; c1 = c; }
        int h0 = wrapH(wr * WS + r0), w0 = wrapH(wc * WS + c0);
        int h1 = wrapH(wr * WS + r1), w1 = wrapH(wc * WS + c1);
        const float* a  = x + ((size_t)((b * HH + h0) * WW + w0)) * CC;
        const float* bb = x + ((size_t)((b * HH + h1) * WW + w1)) * CC;
        float s = 0.f;
        #pragma unroll 4
        for (int ch = 0; ch < CC; ch += 4) {
            float4 av = *(const float4*)(a + ch);
            float4 bv = *(const float4*)(bb + ch);
            s += fabsf(bv.x - av.x) + fabsf(bv.y - av.y) + fabsf(bv.z - av.z) + fabsf(bv.w - av.w);
        }
        if (isH) dh[r0][c0] = s; else dv[r0][c0] = s;
    }
    __syncthreads();

    if (tid < 16) {                     // horizontal cumsum: cth[r][c]
        int r = tid; float acc = 0.f;
        g_cth[win * NTOK + r * 16 + 0] = 0.f;
        for (int c = 1; c < 16; c++) {
            acc += 1.f + sigma * dh[r][c - 1];
            g_cth[win * NTOK + r * 16 + c] = acc;
        }
    } else if (tid < 32) {              // vertical cumsum: ctv[r][c]
        int c = tid - 16; float acc = 0.f;
        g_ctv[win * NTOK + 0 * 16 + c] = 0.f;
        for (int r = 1; r < 16; r++) {
            acc += 1.f + sigma * dv[r - 1][c];
            g_ctv[win * NTOK + r * 16 + c] = acc;
        }
    }
}

// ---------------------------------------------------------------------------
// Kernel 2: attention per (window, head); one thread = one query row.
// No-max softmax. All bias terms (rpi, mask, geo) computed inline.
// Dot + AV accumulate use packed fp32x2 FMA (FFMA2): halves FMA-pipe instrs.
// ---------------------------------------------------------------------------
#define SMEM2_FLOATS (8192 + 8192 + 964 + 256 + 256 + 256)
#define SMEM2_BYTES  (SMEM2_FLOATS * 4)

__global__ void __launch_bounds__(256) attn_kernel(const float* __restrict__ qkv,
                                                   const float* __restrict__ rpb_table,
                                                   const float* __restrict__ geo_scale) {
    extern __shared__ float smem[];
    float* K_sh   = smem;                 // [256][32]
    float* V_sh   = K_sh + 8192;          // [256][32]
    float* rpb_sh = V_sh + 8192;          // [961] (pad 964)
    float* cth_sh = rpb_sh + 964;         // [256]
    float* ctv_sh = cth_sh + 256;         // [256]
    int*   reg_sh = (int*)(ctv_sh + 256); // [256]

    int win = blockIdx.x, head = blockIdx.y;
    int b = win / NWB, wr = (win % NWB) / NWSIDE, wc = win % NWSIDE;
    int q = threadIdx.x;
    int i = q >> 4, j = q & 15;
    int hs = wr * WS + i, ws = wc * WS + j;      // shifted-image coords
    int h = wrapH(hs), w = wrapH(ws);            // original coords

    const float* base = qkv + ((size_t)((b * HH + h) * WW + w)) * (3 * CC) + head * HD;

    // q packed as 16 fp32x2 pairs (d, d+1)
    u64 q2[16];
    #pragma unroll
    for (int d = 0; d < 8; d++) {
        float4 qv = *(const float4*)(base + d * 4);
        q2[2 * d + 0] = pack2(qv.x * QK_SCALE, qv.y * QK_SCALE);
        q2[2 * d + 1] = pack2(qv.z * QK_SCALE, qv.w * QK_SCALE);
        *(float4*)(K_sh + q * HD + d * 4) = *(const float4*)(base + CC + d * 4);
        *(float4*)(V_sh + q * HD + d * 4) = *(const float4*)(base + 2 * CC + d * 4);
    }
    for (int t = q; t < 961; t += 256) rpb_sh[t] = rpb_table[t * NH + head];
    cth_sh[q] = g_cth[win * NTOK + q];
    ctv_sh[q] = g_ctv[win * NTOK + q];
    {   // shift-mask region id (on shifted coords)
        int rh = (hs < HH - WS) ? 0 : ((hs < HH - SHIFT) ? 1 : 2);
        int rw = (ws < WW - WS) ? 0 : ((ws < WW - SHIFT) ? 1 : 2);
        reg_sh[q] = rh * 3 + rw;
    }
    __syncthreads();

    float gsc  = geo_scale[head];
    float cthq = cth_sh[q];
    int myreg  = reg_sh[q];
    int qhi = q & 0xF0;
    int rq = q >> 4, cq = q & 15;

    u64 acc2[16];
    #pragma unroll
    for (int d = 0; d < 16; d++) acc2[d] = 0ull;
    float l = 0.f;

    #pragma unroll 2
    for (int k = 0; k < NTOK; k++) {
        const ulonglong2* kr = (const ulonglong2*)(K_sh + (k << 5));
        u64 da = 0ull, db = 0ull;
        #pragma unroll
        for (int d = 0; d < 8; d++) {
            ulonglong2 kv = kr[d];
            da = ffma2(q2[2 * d + 0], kv.x, da);
            db = ffma2(q2[2 * d + 1], kv.y, db);
        }
        float2 dsum = unpack2(fadd2(da, db));
        float dot = dsum.x + dsum.y;

        int ck = k & 15, rk = k >> 4;
        int gi = qhi | ck;
        float geo = fabsf(cth_sh[gi] - cthq) + fabsf(ctv_sh[k] - ctv_sh[gi]);
        int ridx = (rq - rk + 15) * 31 + (cq - ck + 15);
        float s = dot + rpb_sh[ridx] - gsc * geo + ((myreg == reg_sh[k]) ? 0.f : -100.f);
        float p = __expf(s);
        l += p;

        u64 p2 = pack2(p, p);
        const ulonglong2* vr = (const ulonglong2*)(V_sh + (k << 5));
        #pragma unroll
        for (int d = 0; d < 8; d++) {
            ulonglong2 vv = vr[d];
            acc2[2 * d + 0] = ffma2(p2, vv.x, acc2[2 * d + 0]);
            acc2[2 * d + 1] = ffma2(p2, vv.y, acc2[2 * d + 1]);
        }
    }

    float inv = 1.f / l;
    u64 inv2 = pack2(inv, inv);
    ulonglong2* op = (ulonglong2*)(g_ow + (size_t)win * (NTOK * CC) + q * CC + head * HD);
    #pragma unroll
    for (int d = 0; d < 8; d++) {
        ulonglong2 r;
        r.x = fmul2(acc2[2 * d + 0], inv2);
        r.y = fmul2(acc2[2 * d + 1], inv2);
        op[d] = r;
    }
}

// ---------------------------------------------------------------------------
// Kernel 3: projection (out_win @ proj_w.T + b) + window reverse + roll-back
// Block = 64 tokens; thread = 4 tokens x 12 output channels, fp32x2-packed.
// ---------------------------------------------------------------------------
__global__ void __launch_bounds__(256) proj_kernel(const float* __restrict__ proj_w,
                                                   const float* __restrict__ proj_b,
                                                   float* __restrict__ out) {
    __shared__ float w_sh[32 * 196];   // [kk][cout], pad 196 (16B-aligned rows)
    __shared__ float a_sh[64 * 33];    // [tok][kk], pad 33

    int blk = blockIdx.x, t = threadIdx.x;
    int tok0 = blk * 64;
    int tokl = (t & 15) * 4;
    int cob  = (t >> 4) * 12;

    u64 acc2[24];                      // [tok 0..3][pair 0..5] of 12 outputs
    #pragma unroll
    for (int e = 0; e < 24; e++) acc2[e] = 0ull;

    for (int k0 = 0; k0 < CC; k0 += 32) {
        for (int e = t; e < 2048; e += 256) {
            int tk = e >> 5, kk = e & 31;
            a_sh[tk * 33 + kk] = g_ow[(size_t)(tok0 + tk) * CC + k0 + kk];
        }
        {
            int kk = t & 31;
            for (int co = t >> 5; co < CC; co += 8)
                w_sh[kk * 196 + co] = proj_w[co * CC + k0 + kk];
        }
        __syncthreads();

        #pragma unroll 4
        for (int kk = 0; kk < 32; kk++) {
            u64 ap[4];
            #pragma unroll
            for (int t4 = 0; t4 < 4; t4++) {
                float a = a_sh[(tokl + t4) * 33 + kk];
                ap[t4] = pack2(a, a);
            }
            const ulonglong2* wp = (const ulonglong2*)(w_sh + kk * 196 + cob);
            #pragma unroll
            for (int o2 = 0; o2 < 3; o2++) {
                ulonglong2 wv = wp[o2];
                #pragma unroll
                for (int t4 = 0; t4 < 4; t4++) {
                    acc2[t4 * 6 + o2 * 2 + 0] = ffma2(ap[t4], wv.x, acc2[t4 * 6 + o2 * 2 + 0]);
                    acc2[t4 * 6 + o2 * 2 + 1] = ffma2(ap[t4], wv.y, acc2[t4 * 6 + o2 * 2 + 1]);
                }
            }
        }
        __syncthreads();
    }

    // bias (cob is a multiple of 12 -> 48B offset, 16B aligned)
    const ulonglong2* bp = (const ulonglong2*)(proj_b + cob);
    ulonglong2 bv0 = bp[0], bv1 = bp[1], bv2 = bp[2];
    u64 bb2[6] = { bv0.x, bv0.y, bv1.x, bv1.y, bv2.x, bv2.y };

    #pragma unroll
    for (int ii = 0; ii < 4; ii++) {
        int g = tok0 + tokl + ii;
        int win = g >> 8, tt = g & 255;
        int b = win / NWB, wr = (win % NWB) / NWSIDE, wc = win % NWSIDE;
        int i = tt >> 4, jj = tt & 15;
        int h = wrapH(wr * WS + i), w = wrapH(wc * WS + jj);
        ulonglong2* op = (ulonglong2*)(out + ((size_t)b * (HH * WW) + h * WW + w) * CC + cob);
        #pragma unroll
        for (int o2 = 0; o2 < 3; o2++) {
            ulonglong2 r;
            r.x = fadd2(acc2[ii * 6 + o2 * 2 + 0], bb2[o2 * 2 + 0]);
            r.y = fadd2(acc2[ii * 6 + o2 * 2 + 1], bb2[o2 * 2 + 1]);
            op[o2] = r;
        }
    }
}

// ---------------------------------------------------------------------------
// Launch. Input order per metadata: x, qkv, rpb_table, geo_scale, geo_sigma,
// proj_w, proj_b, rpi (unused), attn_mask (unused), window_size, shift_size,
// num_heads (unused).
// ---------------------------------------------------------------------------
extern "C" void kernel_launch(void* const* d_in, const int* in_sizes, int n_in,
                              void* d_out, int out_size) {
    const float* x        = (const float*)d_in[0];
    const float* qkv      = (const float*)d_in[1];
    const float* rpb      = (const float*)d_in[2];
    const float* gscale   = (const float*)d_in[3];
    const float* gsigma   = (const float*)d_in[4];
    const float* proj_w   = (const float*)d_in[5];
    const float* proj_b   = (const float*)d_in[6];
    float* out            = (float*)d_out;

    cudaFuncSetAttribute(attn_kernel, cudaFuncAttributeMaxDynamicSharedMemorySize, SMEM2_BYTES);

    geo_kernel<<<NWIN, 256>>>(x, gsigma);
    attn_kernel<<<dim3(NWIN, NH), 256, SMEM2_BYTES>>>(qkv, rpb, gscale);
    proj_kernel<<<(NWIN * NTOK) / 64, 256>>>(proj_w, proj_b, out);
}